// round 7
// baseline (speedup 1.0000x reference)
#include <cuda_runtime.h>

#define NA  8400        // anchors / preds per batch
#define NC4 (NA/4)      // float4 columns = 2100
#define NG  2048        // bs*M flattened gts
#define BS  16
#define M   128
#define GTT 8           // gt tile per block (fully unrolled)
#define TPB 128
#define CB  ((NC4 + TPB - 1) / TPB)      // 17 column-blocks
#define DGB (CB * (NG / GTT))            // 17*256 = 4352 dist+giou blocks
#define IOB (CB * (M / GTT) * BS)        // 17*16*16 = 4352 iou blocks

__device__ __forceinline__ float frcp(float a) {
    float r; asm("rcp.approx.f32 %0, %1;" : "=f"(r) : "f"(a)); return r;
}
__device__ __forceinline__ float fsqrt_ap(float a) {
    float r; asm("sqrt.approx.f32 %0, %1;" : "=f"(r) : "f"(a)); return r;
}

// ---------------------------------------------------------------------------
// Fused kernel. Blocks [0, DGB): distances+gious; [DGB, DGB+IOB): IoU.
// Fully unrolled gt tile -> store offsets become immediates, no loop IADDs.
// ---------------------------------------------------------------------------
__global__ __launch_bounds__(TPB)
void fused_kernel(const float4* __restrict__ gt,
                  const float4* __restrict__ pred,
                  const float4* __restrict__ anc,
                  float* __restrict__ dist,
                  float* __restrict__ ovlp,
                  float* __restrict__ giou)
{
    __shared__ float4 sgt[GTT];
    const int tid = threadIdx.x;
    int blk = blockIdx.x;

    if (blk < DGB) {
        // ----- distances + gious -----
        const int cb = blk % CB;
        const int g0 = (blk / CB) * GTT;
        if (tid < GTT) sgt[tid] = gt[g0 + tid];
        __syncthreads();

        const int c = cb * TPB + tid;
        if (c >= NC4) return;
        const int a = 4 * c;

        float Ax[4], Ay[4], Az[4], Aw[4], Acx[4], Acy[4], Awx[4], Awy[4], Aar[4];
        #pragma unroll
        for (int j = 0; j < 4; j++) {
            const float4 A = anc[a + j];
            Ax[j] = A.x; Ay[j] = A.y; Az[j] = A.z; Aw[j] = A.w;
            Acx[j] = 0.5f * (A.x + A.z);
            Acy[j] = 0.5f * (A.y + A.w);
            Awx[j] = A.z - A.x;
            Awy[j] = A.w - A.y;
            Aar[j] = Awx[j] * Awy[j];
        }

        float* pd = dist + (long)g0 * NA + a;
        float* pg = giou + (long)g0 * NA + a;

        #pragma unroll
        for (int k = 0; k < GTT; k++) {
            const float4 gb = sgt[k];
            const float gcx = 0.5f * (gb.x + gb.z);
            const float gcy = 0.5f * (gb.y + gb.w);
            const float tx  = gb.z - gb.x;
            const float ty  = gb.w - gb.y;
            const float area1 = tx * ty;

            float dv[4], gv[4];
            #pragma unroll
            for (int j = 0; j < 4; j++) {
                // distance
                float dx = gcx - Acx[j], dy = gcy - Acy[j];
                dv[j] = fsqrt_ap(fmaf(dx, dx, dy * dy));

                // intersection
                float mxx = fmaxf(gb.x, Ax[j]), mxy = fmaxf(gb.y, Ay[j]);
                float mnz = fminf(gb.z, Az[j]), mnw = fminf(gb.w, Aw[j]);
                float wraw = mnz - mxx;
                float hraw = mnw - mxy;
                float ov   = fmaxf(wraw, 0.0f) * fmaxf(hraw, 0.0f);
                float uni  = (area1 + Aar[j]) - ov;        // >= 16 >> eps

                // enclosure identity: ew = (tx + aw) - wraw
                float ew = (tx + Awx[j]) - wraw;
                float eh = (ty + Awy[j]) - hraw;

                gv[j] = fmaf(ov, frcp(uni), fmaf(uni, frcp(ew * eh), -1.0f));
            }
            __stcs((float4*)(pd + k * NA), make_float4(dv[0], dv[1], dv[2], dv[3]));
            __stcs((float4*)(pg + k * NA), make_float4(gv[0], gv[1], gv[2], gv[3]));
        }
    } else {
        // ----- overlaps (gt vs pred IoU) -----
        blk -= DGB;
        const int cb = blk % CB;
        const int r  = blk / CB;
        const int m0 = (r & 15) * GTT;    // M/GTT == 16
        const int b  = r >> 4;

        if (tid < GTT) sgt[tid] = gt[b * M + m0 + tid];
        __syncthreads();

        const int c = cb * TPB + tid;
        if (c >= NC4) return;
        const int a = 4 * c;

        float Px[4], Py[4], Pz[4], Pw[4], Par[4];
        #pragma unroll
        for (int j = 0; j < 4; j++) {
            const float4 P = pred[b * NA + a + j];
            Px[j] = P.x; Py[j] = P.y; Pz[j] = P.z; Pw[j] = P.w;
            Par[j] = (P.z - P.x) * (P.w - P.y) + 1e-9f;
        }

        float* po = ovlp + ((long)b * M + m0) * NA + a;

        #pragma unroll
        for (int k = 0; k < GTT; k++) {
            const float4 gb = sgt[k];
            const float area1 = (gb.z - gb.x) * (gb.w - gb.y);

            float rv[4];
            #pragma unroll
            for (int j = 0; j < 4; j++) {
                float w = fmaxf(fminf(gb.z, Pz[j]) - fmaxf(gb.x, Px[j]), 0.0f);
                float h = fmaxf(fminf(gb.w, Pw[j]) - fmaxf(gb.y, Py[j]), 0.0f);
                float ov = w * h;
                rv[j] = ov * frcp((area1 + Par[j]) - ov);
            }
            __stcs((float4*)(po + k * NA), make_float4(rv[0], rv[1], rv[2], rv[3]));
        }
    }
}

extern "C" void kernel_launch(void* const* d_in, const int* in_sizes, int n_in,
                              void* d_out, int out_size)
{
    const float4* gt   = (const float4*)d_in[0];
    const float4* pred = (const float4*)d_in[1];
    const float4* anc  = (const float4*)d_in[2];

    float* dist = (float*)d_out;
    float* ovlp = dist + (long)NG * NA;
    float* giou = ovlp + (long)BS * M * NA;

    fused_kernel<<<DGB + IOB, TPB>>>(gt, pred, anc, dist, ovlp, giou);
}